// round 12
// baseline (speedup 1.0000x reference)
#include <cuda_runtime.h>

#define D_MODEL 1024
#define NHEAD   16
#define HD      64
#define SEQ     2048
#define BATCH   4
#define NTOK    (BATCH * SEQ)   // 8192

// Scratch (device globals — allocation-free per harness rules)
__device__ __align__(16) float g_q[BATCH * NHEAD * SEQ * HD];
__device__ __align__(16) float g_k[BATCH * NHEAD * SEQ * HD];
__device__ __align__(16) float g_v[BATCH * NHEAD * SEQ * HD];
__device__ __align__(16) float g_attn[NTOK * D_MODEL];

// ---------------------------------------------------------------------------
// SGEMM core: C = A[M,K] @ W[N,K]^T, 128x128 tile, BK=8, 8x8 per thread,
// 256 threads, register-prefetch pipeline. K = 1024 always here.
// ---------------------------------------------------------------------------

__global__ __launch_bounds__(256) void qkv_gemm(const float* __restrict__ A,
                                                const float* __restrict__ W) {
    const int K = D_MODEL;
    __shared__ __align__(16) float As[8][128];
    __shared__ __align__(16) float Bs[8][128];

    const int tid = threadIdx.x;
    const int m0 = blockIdx.y * 128;
    const int n0 = blockIdx.x * 128;
    const int ar = tid >> 1;
    const int ac = (tid & 1) << 2;
    const int ty = tid >> 4, tx = tid & 15;

    const float* Ap = A + (size_t)(m0 + ar) * K + ac;
    const float* Bp = W + (size_t)(n0 + ar) * K + ac;

    float acc[8][8];
#pragma unroll
    for (int i = 0; i < 8; i++)
#pragma unroll
        for (int j = 0; j < 8; j++) acc[i][j] = 0.f;

    float4 av = *(const float4*)Ap;
    float4 bv = *(const float4*)Bp;

    for (int k0 = 0; k0 < K; k0 += 8) {
        As[ac + 0][ar] = av.x; As[ac + 1][ar] = av.y;
        As[ac + 2][ar] = av.z; As[ac + 3][ar] = av.w;
        Bs[ac + 0][ar] = bv.x; Bs[ac + 1][ar] = bv.y;
        Bs[ac + 2][ar] = bv.z; Bs[ac + 3][ar] = bv.w;
        __syncthreads();
        if (k0 + 8 < K) {
            av = *(const float4*)(Ap + k0 + 8);
            bv = *(const float4*)(Bp + k0 + 8);
        }
#pragma unroll
        for (int kk = 0; kk < 8; kk++) {
            float4 a0 = *(const float4*)&As[kk][ty * 8];
            float4 a1 = *(const float4*)&As[kk][ty * 8 + 4];
            float4 b0 = *(const float4*)&Bs[kk][tx * 8];
            float4 b1 = *(const float4*)&Bs[kk][tx * 8 + 4];
            float a[8] = {a0.x, a0.y, a0.z, a0.w, a1.x, a1.y, a1.z, a1.w};
            float b[8] = {b0.x, b0.y, b0.z, b0.w, b1.x, b1.y, b1.z, b1.w};
#pragma unroll
            for (int i = 0; i < 8; i++)
#pragma unroll
                for (int j = 0; j < 8; j++)
                    acc[i][j] += a[i] * b[j];
        }
        __syncthreads();
    }

    // Epilogue: scatter into Q/K/V laid out [B,H,S,HD]
#pragma unroll
    for (int i = 0; i < 8; i++) {
        int m = m0 + ty * 8 + i;
        int b = m >> 11;        // / SEQ
        int s = m & 2047;       // % SEQ
#pragma unroll
        for (int jj = 0; jj < 8; jj += 4) {
            int n = n0 + tx * 8 + jj;
            int part = n >> 10;          // 0=q 1=k 2=v
            int dj = n & 1023;
            int h = dj >> 6;
            int d = dj & 63;
            float* dst = (part == 0) ? g_q : (part == 1) ? g_k : g_v;
            size_t off = ((size_t)((b * NHEAD + h) * SEQ + s)) * HD + d;
            *(float4*)(dst + off) =
                make_float4(acc[i][jj], acc[i][jj + 1], acc[i][jj + 2], acc[i][jj + 3]);
        }
    }
}

__global__ __launch_bounds__(256) void out_gemm(const float* __restrict__ W,
                                                float* __restrict__ C) {
    const int K = D_MODEL;
    __shared__ __align__(16) float As[8][128];
    __shared__ __align__(16) float Bs[8][128];

    const int tid = threadIdx.x;
    const int m0 = blockIdx.y * 128;
    const int n0 = blockIdx.x * 128;
    const int ar = tid >> 1;
    const int ac = (tid & 1) << 2;
    const int ty = tid >> 4, tx = tid & 15;

    const float* Ap = g_attn + (size_t)(m0 + ar) * K + ac;
    const float* Bp = W + (size_t)(n0 + ar) * K + ac;

    float acc[8][8];
#pragma unroll
    for (int i = 0; i < 8; i++)
#pragma unroll
        for (int j = 0; j < 8; j++) acc[i][j] = 0.f;

    float4 av = *(const float4*)Ap;
    float4 bv = *(const float4*)Bp;

    for (int k0 = 0; k0 < K; k0 += 8) {
        As[ac + 0][ar] = av.x; As[ac + 1][ar] = av.y;
        As[ac + 2][ar] = av.z; As[ac + 3][ar] = av.w;
        Bs[ac + 0][ar] = bv.x; Bs[ac + 1][ar] = bv.y;
        Bs[ac + 2][ar] = bv.z; Bs[ac + 3][ar] = bv.w;
        __syncthreads();
        if (k0 + 8 < K) {
            av = *(const float4*)(Ap + k0 + 8);
            bv = *(const float4*)(Bp + k0 + 8);
        }
#pragma unroll
        for (int kk = 0; kk < 8; kk++) {
            float4 a0 = *(const float4*)&As[kk][ty * 8];
            float4 a1 = *(const float4*)&As[kk][ty * 8 + 4];
            float4 b0 = *(const float4*)&Bs[kk][tx * 8];
            float4 b1 = *(const float4*)&Bs[kk][tx * 8 + 4];
            float a[8] = {a0.x, a0.y, a0.z, a0.w, a1.x, a1.y, a1.z, a1.w};
            float b[8] = {b0.x, b0.y, b0.z, b0.w, b1.x, b1.y, b1.z, b1.w};
#pragma unroll
            for (int i = 0; i < 8; i++)
#pragma unroll
                for (int j = 0; j < 8; j++)
                    acc[i][j] += a[i] * b[j];
        }
        __syncthreads();
    }

#pragma unroll
    for (int i = 0; i < 8; i++) {
        int m = m0 + ty * 8 + i;
#pragma unroll
        for (int jj = 0; jj < 8; jj += 4) {
            int n = n0 + tx * 8 + jj;
            *(float4*)(C + (size_t)m * D_MODEL + n) =
                make_float4(acc[i][jj], acc[i][jj + 1], acc[i][jj + 2], acc[i][jj + 3]);
        }
    }
}

// ---------------------------------------------------------------------------
// Causal flash attention: one block per (b, h, 64-row q tile).
// 256 threads as 16x16; thread (ty,tx) owns S[4ty..4ty+3][4tx..4tx+3] and
// O[4ty..4ty+3][4tx..4tx+3]. Online softmax in registers (half-warp shuffles).
// Smem: Q (64x64), V (64x64), and a union buffer used as K^T (k-major) during
// the S phase and as P during the PV phase. Exactly 48KB static.
// ---------------------------------------------------------------------------

__global__ __launch_bounds__(256) void flash_kernel() {
    __shared__ __align__(16) float Qs[64 * 64];
    __shared__ __align__(16) float Vs[64 * 64];
    __shared__ __align__(16) float KPs[64 * 64];   // K^T, then reused as P

    const int tid = threadIdx.x;
    const int ty = tid >> 4, tx = tid & 15;
    const int qt = blockIdx.x;
    const int bh = blockIdx.y;
    const int b = bh >> 4, h = bh & 15;

    const float* Qg = g_q + ((size_t)bh * SEQ + (size_t)qt * 64) * HD;
    const float* Kg = g_k + (size_t)bh * SEQ * HD;
    const float* Vg = g_v + (size_t)bh * SEQ * HD;

    // Load Q tile, pre-scaled by 1/sqrt(hd) = 0.125
    const float scale = 0.125f;
#pragma unroll
    for (int r = 0; r < 4; r++) {
        int id = tid * 4 + r * 1024;
        int row = id >> 6, d = id & 63;
        float4 v = *(const float4*)(Qg + row * HD + d);
        v.x *= scale; v.y *= scale; v.z *= scale; v.w *= scale;
        *(float4*)&Qs[row * 64 + d] = v;
    }

    float m_i[4], l_i[4], o[4][4];
#pragma unroll
    for (int i = 0; i < 4; i++) {
        m_i[i] = -1e30f; l_i[i] = 0.f;
#pragma unroll
        for (int j = 0; j < 4; j++) o[i][j] = 0.f;
    }

    // K-load mapping: col = tid&63 (conflict-free smem scatter), k chunks by tid>>6
    const int colK = tid & 63;
    const int k0K = (tid >> 6) * 16;

    for (int kt = 0; kt <= qt; kt++) {
        const float* Kt = Kg + (size_t)kt * 64 * HD;
        const float* Vt = Vg + (size_t)kt * 64 * HD;

        // K tile -> KPs transposed [k][col]
#pragma unroll
        for (int r = 0; r < 4; r++) {
            int k = k0K + r * 4;
            float4 kv = *(const float4*)(Kt + colK * HD + k);
            KPs[(k + 0) * 64 + colK] = kv.x;
            KPs[(k + 1) * 64 + colK] = kv.y;
            KPs[(k + 2) * 64 + colK] = kv.z;
            KPs[(k + 3) * 64 + colK] = kv.w;
        }
        // V tile -> Vs [c][d], straight coalesced copy
#pragma unroll
        for (int r = 0; r < 4; r++) {
            int id = tid * 4 + r * 1024;
            int c = id >> 6, d = id & 63;
            *(float4*)&Vs[c * 64 + d] = *(const float4*)(Vt + c * HD + d);
        }
        __syncthreads();

        // S = (Q*scale) @ K^T
        float s[4][4];
#pragma unroll
        for (int i = 0; i < 4; i++)
#pragma unroll
            for (int j = 0; j < 4; j++) s[i][j] = 0.f;

#pragma unroll 8
        for (int k = 0; k < 64; k++) {
            float a0 = Qs[(4 * ty + 0) * 64 + k];
            float a1 = Qs[(4 * ty + 1) * 64 + k];
            float a2 = Qs[(4 * ty + 2) * 64 + k];
            float a3 = Qs[(4 * ty + 3) * 64 + k];
            float b0 = KPs[k * 64 + 4 * tx + 0];
            float b1 = KPs[k * 64 + 4 * tx + 1];
            float b2 = KPs[k * 64 + 4 * tx + 2];
            float b3 = KPs[k * 64 + 4 * tx + 3];
            s[0][0] += a0 * b0; s[0][1] += a0 * b1; s[0][2] += a0 * b2; s[0][3] += a0 * b3;
            s[1][0] += a1 * b0; s[1][1] += a1 * b1; s[1][2] += a1 * b2; s[1][3] += a1 * b3;
            s[2][0] += a2 * b0; s[2][1] += a2 * b1; s[2][2] += a2 * b2; s[2][3] += a2 * b3;
            s[3][0] += a3 * b0; s[3][1] += a3 * b1; s[3][2] += a3 * b2; s[3][3] += a3 * b3;
        }

        if (kt == qt) {  // diagonal tile: causal mask within tile
#pragma unroll
            for (int i = 0; i < 4; i++)
#pragma unroll
                for (int j = 0; j < 4; j++)
                    if (4 * tx + j > 4 * ty + i) s[i][j] = -1e30f;
        }

        __syncthreads();  // done reading K^T; P writes into the same buffer follow

        // Online softmax (half-warp = the 16 threads of one row group)
#pragma unroll
        for (int i = 0; i < 4; i++) {
            float mx = fmaxf(fmaxf(s[i][0], s[i][1]), fmaxf(s[i][2], s[i][3]));
            mx = fmaxf(mx, __shfl_xor_sync(0xffffffffu, mx, 1, 16));
            mx = fmaxf(mx, __shfl_xor_sync(0xffffffffu, mx, 2, 16));
            mx = fmaxf(mx, __shfl_xor_sync(0xffffffffu, mx, 4, 16));
            mx = fmaxf(mx, __shfl_xor_sync(0xffffffffu, mx, 8, 16));
            float mnew = fmaxf(m_i[i], mx);
            float p0 = __expf(s[i][0] - mnew);
            float p1 = __expf(s[i][1] - mnew);
            float p2 = __expf(s[i][2] - mnew);
            float p3 = __expf(s[i][3] - mnew);
            float rs = (p0 + p1) + (p2 + p3);
            rs += __shfl_xor_sync(0xffffffffu, rs, 1, 16);
            rs += __shfl_xor_sync(0xffffffffu, rs, 2, 16);
            rs += __shfl_xor_sync(0xffffffffu, rs, 4, 16);
            rs += __shfl_xor_sync(0xffffffffu, rs, 8, 16);
            float alpha = __expf(m_i[i] - mnew);
            l_i[i] = l_i[i] * alpha + rs;
            m_i[i] = mnew;
            o[i][0] *= alpha; o[i][1] *= alpha; o[i][2] *= alpha; o[i][3] *= alpha;
            *(float4*)&KPs[(4 * ty + i) * 64 + 4 * tx] = make_float4(p0, p1, p2, p3);
        }
        __syncthreads();

        // O += P @ V
#pragma unroll 4
        for (int c = 0; c < 64; c++) {
            float4 v = *(const float4*)&Vs[c * 64 + 4 * tx];
            float p0 = KPs[(4 * ty + 0) * 64 + c];
            float p1 = KPs[(4 * ty + 1) * 64 + c];
            float p2 = KPs[(4 * ty + 2) * 64 + c];
            float p3 = KPs[(4 * ty + 3) * 64 + c];
            o[0][0] += p0 * v.x; o[0][1] += p0 * v.y; o[0][2] += p0 * v.z; o[0][3] += p0 * v.w;
            o[1][0] += p1 * v.x; o[1][1] += p1 * v.y; o[1][2] += p1 * v.z; o[1][3] += p1 * v.w;
            o[2][0] += p2 * v.x; o[2][1] += p2 * v.y; o[2][2] += p2 * v.z; o[2][3] += p2 * v.w;
            o[3][0] += p3 * v.x; o[3][1] += p3 * v.y; o[3][2] += p3 * v.z; o[3][3] += p3 * v.w;
        }
        __syncthreads();
    }

    // Normalize and write to [B,S,D] layout for the out projection
#pragma unroll
    for (int i = 0; i < 4; i++) {
        float inv = 1.0f / l_i[i];
        int qrow = qt * 64 + 4 * ty + i;
        float4 r = make_float4(o[i][0] * inv, o[i][1] * inv, o[i][2] * inv, o[i][3] * inv);
        *(float4*)(g_attn + ((size_t)(b * SEQ + qrow)) * D_MODEL + h * HD + 4 * tx) = r;
    }
}

// ---------------------------------------------------------------------------

extern "C" void kernel_launch(void* const* d_in, const int* in_sizes, int n_in,
                              void* d_out, int out_size) {
    const float* x    = (const float*)d_in[0];   // [4,2048,1024]
    const float* Wqkv = (const float*)d_in[1];   // [3072,1024]
    const float* Wout = (const float*)d_in[2];   // [1024,1024]
    float* out = (float*)d_out;

    dim3 g1((3 * D_MODEL) / 128, NTOK / 128);    // (24, 64)
    qkv_gemm<<<g1, 256>>>(x, Wqkv);

    dim3 g2(SEQ / 64, BATCH * NHEAD);            // (32, 64)
    flash_kernel<<<g2, 256>>>();

    dim3 g3(D_MODEL / 128, NTOK / 128);          // (8, 64)
    out_gemm<<<g3, 256>>>(Wout, out);
}

// round 13
// speedup vs baseline: 1.0093x; 1.0093x over previous
#include <cuda_runtime.h>

#define D_MODEL 1024
#define NHEAD   16
#define HD      64
#define SEQ     2048
#define BATCH   4
#define NTOK    (BATCH * SEQ)   // 8192

// Scratch (device globals — allocation-free per harness rules)
__device__ __align__(16) float g_q[BATCH * NHEAD * SEQ * HD];
__device__ __align__(16) float g_k[BATCH * NHEAD * SEQ * HD];
__device__ __align__(16) float g_v[BATCH * NHEAD * SEQ * HD];
__device__ __align__(16) float g_attn[NTOK * D_MODEL];

// ---------------------------------------------------------------------------
// SGEMM core: C = A[M,K] @ W[N,K]^T, 128x128 tile, BK=8, 8x8 per thread,
// 256 threads, register-prefetch pipeline. K = 1024 always here.
// ---------------------------------------------------------------------------

__global__ __launch_bounds__(256) void qkv_gemm(const float* __restrict__ A,
                                                const float* __restrict__ W) {
    const int K = D_MODEL;
    __shared__ __align__(16) float As[8][128];
    __shared__ __align__(16) float Bs[8][128];

    const int tid = threadIdx.x;
    const int m0 = blockIdx.y * 128;
    const int n0 = blockIdx.x * 128;
    const int ar = tid >> 1;
    const int ac = (tid & 1) << 2;
    const int ty = tid >> 4, tx = tid & 15;

    const float* Ap = A + (size_t)(m0 + ar) * K + ac;
    const float* Bp = W + (size_t)(n0 + ar) * K + ac;

    float acc[8][8];
#pragma unroll
    for (int i = 0; i < 8; i++)
#pragma unroll
        for (int j = 0; j < 8; j++) acc[i][j] = 0.f;

    float4 av = *(const float4*)Ap;
    float4 bv = *(const float4*)Bp;

    for (int k0 = 0; k0 < K; k0 += 8) {
        As[ac + 0][ar] = av.x; As[ac + 1][ar] = av.y;
        As[ac + 2][ar] = av.z; As[ac + 3][ar] = av.w;
        Bs[ac + 0][ar] = bv.x; Bs[ac + 1][ar] = bv.y;
        Bs[ac + 2][ar] = bv.z; Bs[ac + 3][ar] = bv.w;
        __syncthreads();
        if (k0 + 8 < K) {
            av = *(const float4*)(Ap + k0 + 8);
            bv = *(const float4*)(Bp + k0 + 8);
        }
#pragma unroll
        for (int kk = 0; kk < 8; kk++) {
            float4 a0 = *(const float4*)&As[kk][ty * 8];
            float4 a1 = *(const float4*)&As[kk][ty * 8 + 4];
            float4 b0 = *(const float4*)&Bs[kk][tx * 8];
            float4 b1 = *(const float4*)&Bs[kk][tx * 8 + 4];
            float a[8] = {a0.x, a0.y, a0.z, a0.w, a1.x, a1.y, a1.z, a1.w};
            float b[8] = {b0.x, b0.y, b0.z, b0.w, b1.x, b1.y, b1.z, b1.w};
#pragma unroll
            for (int i = 0; i < 8; i++)
#pragma unroll
                for (int j = 0; j < 8; j++)
                    acc[i][j] += a[i] * b[j];
        }
        __syncthreads();
    }

    // Epilogue: scatter into Q/K/V laid out [B,H,S,HD]
#pragma unroll
    for (int i = 0; i < 8; i++) {
        int m = m0 + ty * 8 + i;
        int b = m >> 11;        // / SEQ
        int s = m & 2047;       // % SEQ
#pragma unroll
        for (int jj = 0; jj < 8; jj += 4) {
            int n = n0 + tx * 8 + jj;
            int part = n >> 10;          // 0=q 1=k 2=v
            int dj = n & 1023;
            int h = dj >> 6;
            int d = dj & 63;
            float* dst = (part == 0) ? g_q : (part == 1) ? g_k : g_v;
            size_t off = ((size_t)((b * NHEAD + h) * SEQ + s)) * HD + d;
            *(float4*)(dst + off) =
                make_float4(acc[i][jj], acc[i][jj + 1], acc[i][jj + 2], acc[i][jj + 3]);
        }
    }
}

__global__ __launch_bounds__(256) void out_gemm(const float* __restrict__ W,
                                                float* __restrict__ C) {
    const int K = D_MODEL;
    __shared__ __align__(16) float As[8][128];
    __shared__ __align__(16) float Bs[8][128];

    const int tid = threadIdx.x;
    const int m0 = blockIdx.y * 128;
    const int n0 = blockIdx.x * 128;
    const int ar = tid >> 1;
    const int ac = (tid & 1) << 2;
    const int ty = tid >> 4, tx = tid & 15;

    const float* Ap = g_attn + (size_t)(m0 + ar) * K + ac;
    const float* Bp = W + (size_t)(n0 + ar) * K + ac;

    float acc[8][8];
#pragma unroll
    for (int i = 0; i < 8; i++)
#pragma unroll
        for (int j = 0; j < 8; j++) acc[i][j] = 0.f;

    float4 av = *(const float4*)Ap;
    float4 bv = *(const float4*)Bp;

    for (int k0 = 0; k0 < K; k0 += 8) {
        As[ac + 0][ar] = av.x; As[ac + 1][ar] = av.y;
        As[ac + 2][ar] = av.z; As[ac + 3][ar] = av.w;
        Bs[ac + 0][ar] = bv.x; Bs[ac + 1][ar] = bv.y;
        Bs[ac + 2][ar] = bv.z; Bs[ac + 3][ar] = bv.w;
        __syncthreads();
        if (k0 + 8 < K) {
            av = *(const float4*)(Ap + k0 + 8);
            bv = *(const float4*)(Bp + k0 + 8);
        }
#pragma unroll
        for (int kk = 0; kk < 8; kk++) {
            float4 a0 = *(const float4*)&As[kk][ty * 8];
            float4 a1 = *(const float4*)&As[kk][ty * 8 + 4];
            float4 b0 = *(const float4*)&Bs[kk][tx * 8];
            float4 b1 = *(const float4*)&Bs[kk][tx * 8 + 4];
            float a[8] = {a0.x, a0.y, a0.z, a0.w, a1.x, a1.y, a1.z, a1.w};
            float b[8] = {b0.x, b0.y, b0.z, b0.w, b1.x, b1.y, b1.z, b1.w};
#pragma unroll
            for (int i = 0; i < 8; i++)
#pragma unroll
                for (int j = 0; j < 8; j++)
                    acc[i][j] += a[i] * b[j];
        }
        __syncthreads();
    }

#pragma unroll
    for (int i = 0; i < 8; i++) {
        int m = m0 + ty * 8 + i;
#pragma unroll
        for (int jj = 0; jj < 8; jj += 4) {
            int n = n0 + tx * 8 + jj;
            *(float4*)(C + (size_t)m * D_MODEL + n) =
                make_float4(acc[i][jj], acc[i][jj + 1], acc[i][jj + 2], acc[i][jj + 3]);
        }
    }
}

// ---------------------------------------------------------------------------
// Causal flash attention: one block per (b, h, 64-row q tile).
// 256 threads as 16x16; thread (ty,tx) owns S[4ty..4ty+3][4tx..4tx+3] and
// O[4ty..4ty+3][4tx..4tx+3]. Online softmax in registers (half-warp shuffles).
// Smem: Q (64x64), V (64x64), and a union buffer used as K^T (k-major) during
// the S phase and as P during the PV phase. Exactly 48KB static.
// ---------------------------------------------------------------------------

__global__ __launch_bounds__(256) void flash_kernel() {
    __shared__ __align__(16) float Qs[64 * 64];
    __shared__ __align__(16) float Vs[64 * 64];
    __shared__ __align__(16) float KPs[64 * 64];   // K^T, then reused as P

    const int tid = threadIdx.x;
    const int ty = tid >> 4, tx = tid & 15;
    const int qt = blockIdx.x;
    const int bh = blockIdx.y;
    const int b = bh >> 4, h = bh & 15;

    const float* Qg = g_q + ((size_t)bh * SEQ + (size_t)qt * 64) * HD;
    const float* Kg = g_k + (size_t)bh * SEQ * HD;
    const float* Vg = g_v + (size_t)bh * SEQ * HD;

    // Load Q tile, pre-scaled by 1/sqrt(hd) = 0.125
    const float scale = 0.125f;
#pragma unroll
    for (int r = 0; r < 4; r++) {
        int id = tid * 4 + r * 1024;
        int row = id >> 6, d = id & 63;
        float4 v = *(const float4*)(Qg + row * HD + d);
        v.x *= scale; v.y *= scale; v.z *= scale; v.w *= scale;
        *(float4*)&Qs[row * 64 + d] = v;
    }

    float m_i[4], l_i[4], o[4][4];
#pragma unroll
    for (int i = 0; i < 4; i++) {
        m_i[i] = -1e30f; l_i[i] = 0.f;
#pragma unroll
        for (int j = 0; j < 4; j++) o[i][j] = 0.f;
    }

    // K-load mapping: col = tid&63 (conflict-free smem scatter), k chunks by tid>>6
    const int colK = tid & 63;
    const int k0K = (tid >> 6) * 16;

    for (int kt = 0; kt <= qt; kt++) {
        const float* Kt = Kg + (size_t)kt * 64 * HD;
        const float* Vt = Vg + (size_t)kt * 64 * HD;

        // K tile -> KPs transposed [k][col]
#pragma unroll
        for (int r = 0; r < 4; r++) {
            int k = k0K + r * 4;
            float4 kv = *(const float4*)(Kt + colK * HD + k);
            KPs[(k + 0) * 64 + colK] = kv.x;
            KPs[(k + 1) * 64 + colK] = kv.y;
            KPs[(k + 2) * 64 + colK] = kv.z;
            KPs[(k + 3) * 64 + colK] = kv.w;
        }
        // V tile -> Vs [c][d], straight coalesced copy
#pragma unroll
        for (int r = 0; r < 4; r++) {
            int id = tid * 4 + r * 1024;
            int c = id >> 6, d = id & 63;
            *(float4*)&Vs[c * 64 + d] = *(const float4*)(Vt + c * HD + d);
        }
        __syncthreads();

        // S = (Q*scale) @ K^T
        float s[4][4];
#pragma unroll
        for (int i = 0; i < 4; i++)
#pragma unroll
            for (int j = 0; j < 4; j++) s[i][j] = 0.f;

#pragma unroll 8
        for (int k = 0; k < 64; k++) {
            float a0 = Qs[(4 * ty + 0) * 64 + k];
            float a1 = Qs[(4 * ty + 1) * 64 + k];
            float a2 = Qs[(4 * ty + 2) * 64 + k];
            float a3 = Qs[(4 * ty + 3) * 64 + k];
            float b0 = KPs[k * 64 + 4 * tx + 0];
            float b1 = KPs[k * 64 + 4 * tx + 1];
            float b2 = KPs[k * 64 + 4 * tx + 2];
            float b3 = KPs[k * 64 + 4 * tx + 3];
            s[0][0] += a0 * b0; s[0][1] += a0 * b1; s[0][2] += a0 * b2; s[0][3] += a0 * b3;
            s[1][0] += a1 * b0; s[1][1] += a1 * b1; s[1][2] += a1 * b2; s[1][3] += a1 * b3;
            s[2][0] += a2 * b0; s[2][1] += a2 * b1; s[2][2] += a2 * b2; s[2][3] += a2 * b3;
            s[3][0] += a3 * b0; s[3][1] += a3 * b1; s[3][2] += a3 * b2; s[3][3] += a3 * b3;
        }

        if (kt == qt) {  // diagonal tile: causal mask within tile
#pragma unroll
            for (int i = 0; i < 4; i++)
#pragma unroll
                for (int j = 0; j < 4; j++)
                    if (4 * tx + j > 4 * ty + i) s[i][j] = -1e30f;
        }

        __syncthreads();  // done reading K^T; P writes into the same buffer follow

        // Online softmax (half-warp = the 16 threads of one row group)
#pragma unroll
        for (int i = 0; i < 4; i++) {
            float mx = fmaxf(fmaxf(s[i][0], s[i][1]), fmaxf(s[i][2], s[i][3]));
            mx = fmaxf(mx, __shfl_xor_sync(0xffffffffu, mx, 1, 16));
            mx = fmaxf(mx, __shfl_xor_sync(0xffffffffu, mx, 2, 16));
            mx = fmaxf(mx, __shfl_xor_sync(0xffffffffu, mx, 4, 16));
            mx = fmaxf(mx, __shfl_xor_sync(0xffffffffu, mx, 8, 16));
            float mnew = fmaxf(m_i[i], mx);
            float p0 = __expf(s[i][0] - mnew);
            float p1 = __expf(s[i][1] - mnew);
            float p2 = __expf(s[i][2] - mnew);
            float p3 = __expf(s[i][3] - mnew);
            float rs = (p0 + p1) + (p2 + p3);
            rs += __shfl_xor_sync(0xffffffffu, rs, 1, 16);
            rs += __shfl_xor_sync(0xffffffffu, rs, 2, 16);
            rs += __shfl_xor_sync(0xffffffffu, rs, 4, 16);
            rs += __shfl_xor_sync(0xffffffffu, rs, 8, 16);
            float alpha = __expf(m_i[i] - mnew);
            l_i[i] = l_i[i] * alpha + rs;
            m_i[i] = mnew;
            o[i][0] *= alpha; o[i][1] *= alpha; o[i][2] *= alpha; o[i][3] *= alpha;
            *(float4*)&KPs[(4 * ty + i) * 64 + 4 * tx] = make_float4(p0, p1, p2, p3);
        }
        __syncthreads();

        // O += P @ V
#pragma unroll 4
        for (int c = 0; c < 64; c++) {
            float4 v = *(const float4*)&Vs[c * 64 + 4 * tx];
            float p0 = KPs[(4 * ty + 0) * 64 + c];
            float p1 = KPs[(4 * ty + 1) * 64 + c];
            float p2 = KPs[(4 * ty + 2) * 64 + c];
            float p3 = KPs[(4 * ty + 3) * 64 + c];
            o[0][0] += p0 * v.x; o[0][1] += p0 * v.y; o[0][2] += p0 * v.z; o[0][3] += p0 * v.w;
            o[1][0] += p1 * v.x; o[1][1] += p1 * v.y; o[1][2] += p1 * v.z; o[1][3] += p1 * v.w;
            o[2][0] += p2 * v.x; o[2][1] += p2 * v.y; o[2][2] += p2 * v.z; o[2][3] += p2 * v.w;
            o[3][0] += p3 * v.x; o[3][1] += p3 * v.y; o[3][2] += p3 * v.z; o[3][3] += p3 * v.w;
        }
        __syncthreads();
    }

    // Normalize and write to [B,S,D] layout for the out projection
#pragma unroll
    for (int i = 0; i < 4; i++) {
        float inv = 1.0f / l_i[i];
        int qrow = qt * 64 + 4 * ty + i;
        float4 r = make_float4(o[i][0] * inv, o[i][1] * inv, o[i][2] * inv, o[i][3] * inv);
        *(float4*)(g_attn + ((size_t)(b * SEQ + qrow)) * D_MODEL + h * HD + 4 * tx) = r;
    }
}

// ---------------------------------------------------------------------------

extern "C" void kernel_launch(void* const* d_in, const int* in_sizes, int n_in,
                              void* d_out, int out_size) {
    const float* x    = (const float*)d_in[0];   // [4,2048,1024]
    const float* Wqkv = (const float*)d_in[1];   // [3072,1024]
    const float* Wout = (const float*)d_in[2];   // [1024,1024]
    float* out = (float*)d_out;

    dim3 g1((3 * D_MODEL) / 128, NTOK / 128);    // (24, 64)
    qkv_gemm<<<g1, 256>>>(x, Wqkv);

    dim3 g2(SEQ / 64, BATCH * NHEAD);            // (32, 64)
    flash_kernel<<<g2, 256>>>();

    dim3 g3(D_MODEL / 128, NTOK / 128);          // (8, 64)
    out_gemm<<<g3, 256>>>(Wout, out);
}